// round 9
// baseline (speedup 1.0000x reference)
#include <cuda_runtime.h>
#include <math.h>

#define N_CLUS 64
#define C_DIM 768
#define B_DIM 8
#define H_IN 32
#define HW 1024                          // 32*32
#define OUT_HW 512
#define PLANE (OUT_HW * OUT_HW)          // 262144
#define NPIX (B_DIM * HW)                // 8192
#define RES_ELEMS ((size_t)B_DIM * N_CLUS * PLANE)   // 134217728
#define CODE_ELEMS ((size_t)B_DIM * C_DIM * HW)      // 6291456
#define KC 32

__device__ int   g_assign[NPIX];
__device__ float g_maxcos[NPIX];

// ---- packed fp32x2 helpers (Blackwell FFMA2) ----
__device__ __forceinline__ unsigned long long splat2(float x) {
    unsigned long long r;
    unsigned u = __float_as_uint(x);
    asm("mov.b64 %0, {%1, %2};" : "=l"(r) : "r"(u), "r"(u));
    return r;
}
__device__ __forceinline__ float2 unpack2(unsigned long long v) {
    unsigned lo, hi;
    asm("mov.b64 {%0, %1}, %2;" : "=r"(lo), "=r"(hi) : "l"(v));
    return make_float2(__uint_as_float(lo), __uint_as_float(hi));
}
#define FMA2(d, a, b) \
    asm("fma.rn.f32x2 %0, %1, %2, %0;" : "+l"(d) : "l"(a), "l"(b))

// ---------------------------------------------------------------------------
// simK (R7-proven): cluster norms + cosine sims + per-pixel argmax.
// 128 blocks x 256 thr. Block = 64 px x 64 clusters.
// Thread = 4 px (pid) x 4 clusters (ng). FFMA2 packed inner loop.
// ---------------------------------------------------------------------------
__global__ __launch_bounds__(256) void simK(const float* __restrict__ code,
                                            const float* __restrict__ clusters) {
    const int tid = threadIdx.x;
    const int blk = blockIdx.x;
    const int wid = tid >> 5;
    const int lid = tid & 31;

    __shared__ __align__(16) float codeS[KC][64];
    __shared__ __align__(16) float clusG[16][132];   // [ng][c*4+j], pad->132
    __shared__ float sinv[N_CLUS];

    // cluster inverse norms: warp w -> rows 8w..8w+7, lane-strided + shfl
#pragma unroll
    for (int q = 0; q < 8; ++q) {
        const int n = wid * 8 + q;
        const float* cr = clusters + n * C_DIM;
        float s = 0.f;
#pragma unroll
        for (int i = 0; i < C_DIM / 32; ++i) {
            float v = __ldg(cr + lid + i * 32);
            s = fmaf(v, v, s);
        }
#pragma unroll
        for (int o = 16; o > 0; o >>= 1) s += __shfl_xor_sync(0xffffffffu, s, o);
        if (lid == 0) sinv[n] = 1.f / fmaxf(sqrtf(s), 1e-12f);
    }
    __syncthreads();

    const int b = blk >> 4;                  // 16 blocks per image
    const int hwbase = (blk & 15) * 64;
    const int pid = tid >> 4;                // pixel quad: px 4*pid..4*pid+3
    const int ng = tid & 15;                 // cluster group: n = 4*ng..4*ng+3
    const float* codeb = code + (size_t)b * C_DIM * HW + hwbase;

    // acc2[p][h]: h=0 packs clusters (4ng+0,4ng+1), h=1 packs (4ng+2,4ng+3)
    unsigned long long acc2[4][2];
#pragma unroll
    for (int p = 0; p < 4; ++p) { acc2[p][0] = 0ull; acc2[p][1] = 0ull; }
    float ssq[4] = {0.f, 0.f, 0.f, 0.f};

    for (int c0 = 0; c0 < C_DIM; c0 += KC) {
#pragma unroll
        for (int k = 0; k < 8; ++k) {        // stage code [KC][64], coalesced
            int idx = tid + k * 256;
            int c = idx >> 6, px = idx & 63;
            codeS[c][px] = codeb[(size_t)(c0 + c) * HW + px];
        }
#pragma unroll
        for (int k = 0; k < 8; ++k) {        // stage normed clusters [ng][c][j]
            int idx = tid + k * 256;
            int g = idx >> 7, rr = idx & 127;
            int j = rr & 3, c = rr >> 2;
            int n = g * 4 + j;
            clusG[g][c * 4 + j] = clusters[n * C_DIM + c0 + c] * sinv[n];
        }
        __syncthreads();

#pragma unroll 4
        for (int c = 0; c < KC; ++c) {
            float4 a = *(const float4*)&codeS[c][4 * pid];
            ulonglong2 bp = *(const ulonglong2*)&clusG[ng][4 * c];
            if (ng == 0) {                   // fold feature sumsq into pass
                ssq[0] = fmaf(a.x, a.x, ssq[0]);
                ssq[1] = fmaf(a.y, a.y, ssq[1]);
                ssq[2] = fmaf(a.z, a.z, ssq[2]);
                ssq[3] = fmaf(a.w, a.w, ssq[3]);
            }
            unsigned long long ax = splat2(a.x), ay = splat2(a.y);
            unsigned long long az = splat2(a.z), aw = splat2(a.w);
            FMA2(acc2[0][0], ax, bp.x);  FMA2(acc2[0][1], ax, bp.y);
            FMA2(acc2[1][0], ay, bp.x);  FMA2(acc2[1][1], ay, bp.y);
            FMA2(acc2[2][0], az, bp.x);  FMA2(acc2[2][1], az, bp.y);
            FMA2(acc2[3][0], aw, bp.x);  FMA2(acc2[3][1], aw, bp.y);
        }
        __syncthreads();
    }

    // per-pixel argmax: local over 4 clusters, then shfl tree over 16-lane
    // group. Higher lane == higher n; strict '>' keeps first-max tiebreak.
#pragma unroll
    for (int p = 0; p < 4; ++p) {
        float2 j01 = unpack2(acc2[p][0]);
        float2 j23 = unpack2(acc2[p][1]);
        float av[4] = {j01.x, j01.y, j23.x, j23.y};
        float mv = av[0];
        int mn = ng * 4;
#pragma unroll
        for (int j = 1; j < 4; ++j)
            if (av[j] > mv) { mv = av[j]; mn = ng * 4 + j; }
#pragma unroll
        for (int off = 8; off > 0; off >>= 1) {
            float ov = __shfl_down_sync(0xffffffffu, mv, off, 16);
            int   on = __shfl_down_sync(0xffffffffu, mn, off, 16);
            if (ov > mv) { mv = ov; mn = on; }
        }
        if (ng == 0) {
            const int gp = blk * 64 + 4 * pid + p;   // b*1024 + hw index
            g_assign[gp] = mn;
            g_maxcos[gp] = mv / fmaxf(sqrtf(ssq[p]), 1e-12f);
        }
    }
}

// ---------------------------------------------------------------------------
// lossK: deterministic reduction of max cosine sims. 1 block x 256 thr.
// ---------------------------------------------------------------------------
__global__ void lossK(float* __restrict__ out) {
    __shared__ float red[256];
    float s = 0.f;
    for (int i = threadIdx.x; i < NPIX; i += 256) s += g_maxcos[i];
    red[threadIdx.x] = s;
    __syncthreads();
    for (int o = 128; o > 0; o >>= 1) {
        if (threadIdx.x < o) red[threadIdx.x] += red[threadIdx.x + o];
        __syncthreads();
    }
    if (threadIdx.x == 0) out[0] = -red[0] / (float)NPIX;
}

// ---------------------------------------------------------------------------
// scatterK: sparse bilinear scatter over the pre-zeroed output.
// Grid (2, 512, 8) x 256 thr: thread = one x of one (b, y) row.
// <=4 nonzero plane-values per (y,x); duplicates merged in-thread.
// ---------------------------------------------------------------------------
__global__ __launch_bounds__(256) void scatterK(float* __restrict__ out) {
    const int b = blockIdx.z;
    const int y = blockIdx.y;
    const int x = blockIdx.x * 256 + threadIdx.x;

    const float fy = (y + 0.5f) * 0.0625f - 0.5f;
    const float y0f = floorf(fy);
    const float wy1 = fy - y0f, wy0 = 1.f - wy1;
    const int y0 = (int)y0f;
    const int ylo = max(y0, 0), yhi = min(y0 + 1, H_IN - 1);
    const int* A0 = g_assign + b * HW + ylo * H_IN;
    const int* A1 = g_assign + b * HW + yhi * H_IN;

    const float fx = (x + 0.5f) * 0.0625f - 0.5f;
    const float x0f = floorf(fx);
    const float wx1 = fx - x0f, wx0 = 1.f - wx1;
    const int x0 = (int)x0f;
    const int xlo = max(x0, 0), xhi = min(x0 + 1, H_IN - 1);

    int nn[4]; float w[4];
    nn[0] = __ldg(A0 + xlo); w[0] = wy0 * wx0;
    nn[1] = __ldg(A0 + xhi); w[1] = wy0 * wx1;
    nn[2] = __ldg(A1 + xlo); w[2] = wy1 * wx0;
    nn[3] = __ldg(A1 + xhi); w[3] = wy1 * wx1;

    bool v[4] = {true, true, true, true};
#pragma unroll
    for (int i = 1; i < 4; ++i)
#pragma unroll
        for (int j = 0; j < i; ++j)
            if (v[i] && v[j] && nn[i] == nn[j]) { w[j] += w[i]; v[i] = false; }

    float* base = out + 1 + (size_t)b * N_CLUS * PLANE + (size_t)y * OUT_HW + x;
#pragma unroll
    for (int i = 0; i < 4; ++i)
        if (v[i]) base[(size_t)nn[i] * PLANE] = w[i];
}

// ---------------------------------------------------------------------------
// Graph with two parallel branches (event fork/join, capture-legal):
//   s2:      memset(resized region)                      [~537MB dense write]
//   legacy:  simK -> lossK -> memcpy(code passthrough)   [hidden under memset]
//   join:    scatterK (needs memset AND sim)
// Stream/events created once on the first (uncaptured) correctness call.
// out layout = [loss(1)] [resized(134217728)] [code(6291456)]
// ---------------------------------------------------------------------------
extern "C" void kernel_launch(void* const* d_in, const int* in_sizes, int n_in,
                              void* d_out, int out_size) {
    const float* code = (const float*)d_in[0];
    const float* clusters = (const float*)d_in[1];
    float* out = (float*)d_out;

    static cudaStream_t s2 = 0;
    static cudaEvent_t evF = 0, evJ = 0;
    if (s2 == 0) {
        cudaStreamCreateWithFlags(&s2, cudaStreamNonBlocking);
        cudaEventCreateWithFlags(&evF, cudaEventDisableTiming);
        cudaEventCreateWithFlags(&evJ, cudaEventDisableTiming);
    }

    // fork: s2 branch does the dense zero-fill
    cudaEventRecord(evF, 0);
    cudaStreamWaitEvent(s2, evF, 0);
    cudaMemsetAsync(out + 1, 0, RES_ELEMS * sizeof(float), s2);

    // legacy branch: sim -> loss -> code copy (overlaps the memset)
    simK<<<128, 256>>>(code, clusters);
    lossK<<<1, 256>>>(out);
    cudaMemcpyAsync(out + 1 + RES_ELEMS, code, CODE_ELEMS * sizeof(float),
                    cudaMemcpyDeviceToDevice, 0);

    // join: scatter needs both the zeroed canvas and the assignments
    cudaEventRecord(evJ, s2);
    cudaStreamWaitEvent(0, evJ, 0);
    dim3 gs(2, OUT_HW, B_DIM);
    scatterK<<<gs, 256>>>(out);
}

// round 10
// speedup vs baseline: 1.3234x; 1.3234x over previous
#include <cuda_runtime.h>
#include <math.h>

#define N_CLUS 64
#define C_DIM 768
#define B_DIM 8
#define H_IN 32
#define HW 1024                          // 32*32
#define OUT_HW 512
#define PLANE (OUT_HW * OUT_HW)          // 262144
#define NPIX (B_DIM * HW)                // 8192
#define RES_ELEMS ((size_t)B_DIM * N_CLUS * PLANE)   // 134217728
#define CODE_ELEMS ((size_t)B_DIM * C_DIM * HW)      // 6291456
#define KC 32

#define FILL_BLOCKS 4096                 // writeK: one per (b, y)
#define COPY_BLOCKS 128
#define W_BLOCKS (FILL_BLOCKS + COPY_BLOCKS + 1)   // +1 loss block

__device__ int   g_assign[NPIX];
__device__ float g_maxcos[NPIX];

// ---- packed fp32x2 helpers (Blackwell FFMA2) ----
__device__ __forceinline__ unsigned long long splat2(float x) {
    unsigned long long r;
    unsigned u = __float_as_uint(x);
    asm("mov.b64 %0, {%1, %2};" : "=l"(r) : "r"(u), "r"(u));
    return r;
}
__device__ __forceinline__ float2 unpack2(unsigned long long v) {
    unsigned lo, hi;
    asm("mov.b64 {%0, %1}, %2;" : "=r"(lo), "=r"(hi) : "l"(v));
    return make_float2(__uint_as_float(lo), __uint_as_float(hi));
}
#define FMA2(d, a, b) \
    asm("fma.rn.f32x2 %0, %1, %2, %0;" : "+l"(d) : "l"(a), "l"(b))

// ---------------------------------------------------------------------------
// simK: cluster norms + cosine sims + per-pixel argmax.
// 256 blocks x 128 thr (>=2 co-resident blocks on most SMs).
// Block = 32 px x 64 clusters. Thread = 4 px (pid 0..7) x 4 clus (ng 0..15).
// Same per-thread FFMA2 shape as the proven R7 kernel (2B LDS per MAC).
// ---------------------------------------------------------------------------
__global__ __launch_bounds__(128) void simK(const float* __restrict__ code,
                                            const float* __restrict__ clusters) {
    const int tid = threadIdx.x;
    const int blk = blockIdx.x;
    const int wid = tid >> 5;            // 4 warps
    const int lid = tid & 31;

    __shared__ __align__(16) float codeS[KC][32];    // 4KB
    __shared__ __align__(16) float clusG[16][132];   // [ng][c*4+j], pad->132
    __shared__ float sinv[N_CLUS];

    // cluster inverse norms: warp w -> rows 16w..16w+15, lane-strided + shfl
#pragma unroll
    for (int q = 0; q < 16; ++q) {
        const int n = wid * 16 + q;
        const float* cr = clusters + n * C_DIM;
        float s = 0.f;
#pragma unroll
        for (int i = 0; i < C_DIM / 32; ++i) {
            float v = __ldg(cr + lid + i * 32);
            s = fmaf(v, v, s);
        }
#pragma unroll
        for (int o = 16; o > 0; o >>= 1) s += __shfl_xor_sync(0xffffffffu, s, o);
        if (lid == 0) sinv[n] = 1.f / fmaxf(sqrtf(s), 1e-12f);
    }
    __syncthreads();

    const int b = blk >> 5;                  // 32 blocks per image
    const int hwbase = (blk & 31) * 32;
    const int pid = tid >> 4;                // pixel quad: px 4*pid..4*pid+3
    const int ng = tid & 15;                 // cluster group: n = 4*ng..4*ng+3
    const float* codeb = code + (size_t)b * C_DIM * HW + hwbase;

    // acc2[p][h]: h=0 packs clusters (4ng+0,4ng+1), h=1 packs (4ng+2,4ng+3)
    unsigned long long acc2[4][2];
#pragma unroll
    for (int p = 0; p < 4; ++p) { acc2[p][0] = 0ull; acc2[p][1] = 0ull; }
    float ssq[4] = {0.f, 0.f, 0.f, 0.f};

    for (int c0 = 0; c0 < C_DIM; c0 += KC) {
#pragma unroll
        for (int k = 0; k < 8; ++k) {        // stage code [KC][32], coalesced
            int idx = tid + k * 128;
            int c = idx >> 5, px = idx & 31;
            codeS[c][px] = codeb[(size_t)(c0 + c) * HW + px];
        }
#pragma unroll
        for (int k = 0; k < 16; ++k) {       // stage normed clusters [ng][c][j]
            int idx = tid + k * 128;
            int g = idx >> 7, rr = idx & 127;
            int j = rr & 3, c = rr >> 2;
            int n = g * 4 + j;
            clusG[g][c * 4 + j] = clusters[n * C_DIM + c0 + c] * sinv[n];
        }
        __syncthreads();

#pragma unroll 4
        for (int c = 0; c < KC; ++c) {
            float4 a = *(const float4*)&codeS[c][4 * pid];
            ulonglong2 bp = *(const ulonglong2*)&clusG[ng][4 * c];
            if (ng == 0) {                   // fold feature sumsq into pass
                ssq[0] = fmaf(a.x, a.x, ssq[0]);
                ssq[1] = fmaf(a.y, a.y, ssq[1]);
                ssq[2] = fmaf(a.z, a.z, ssq[2]);
                ssq[3] = fmaf(a.w, a.w, ssq[3]);
            }
            unsigned long long ax = splat2(a.x), ay = splat2(a.y);
            unsigned long long az = splat2(a.z), aw = splat2(a.w);
            FMA2(acc2[0][0], ax, bp.x);  FMA2(acc2[0][1], ax, bp.y);
            FMA2(acc2[1][0], ay, bp.x);  FMA2(acc2[1][1], ay, bp.y);
            FMA2(acc2[2][0], az, bp.x);  FMA2(acc2[2][1], az, bp.y);
            FMA2(acc2[3][0], aw, bp.x);  FMA2(acc2[3][1], aw, bp.y);
        }
        __syncthreads();
    }

    // per-pixel argmax: local over 4 clusters, then shfl tree over the
    // 16-lane group (threads of one pid are lanes [16*pid%32 ..)+16).
    // Higher lane == higher n; strict '>' keeps first-max (lowest n) tiebreak.
#pragma unroll
    for (int p = 0; p < 4; ++p) {
        float2 j01 = unpack2(acc2[p][0]);
        float2 j23 = unpack2(acc2[p][1]);
        float av[4] = {j01.x, j01.y, j23.x, j23.y};
        float mv = av[0];
        int mn = ng * 4;
#pragma unroll
        for (int j = 1; j < 4; ++j)
            if (av[j] > mv) { mv = av[j]; mn = ng * 4 + j; }
#pragma unroll
        for (int off = 8; off > 0; off >>= 1) {
            float ov = __shfl_down_sync(0xffffffffu, mv, off, 16);
            int   on = __shfl_down_sync(0xffffffffu, mn, off, 16);
            if (ov > mv) { mv = ov; mn = on; }
        }
        if (ng == 0) {
            const int gp = blk * 32 + 4 * pid + p;   // b*1024 + hw index
            g_assign[gp] = mn;
            g_maxcos[gp] = mv / fmaxf(sqrtf(ssq[p]), 1e-12f);
        }
    }
}

// ---------------------------------------------------------------------------
// writeK (R7-proven, 122.4us): single-pass direct write + copy + loss.
//   blocks [0,4096):      (b,y) row across all 64 planes. Thread owns one
//                         aligned float4 slot; precomputes bilinear candidates
//                         + 64-bit nonzero-plane mask; 1 STG.128 per plane.
//   blocks [4096,4224):   code passthrough copy
//   block  4224:          deterministic loss reduction
// ---------------------------------------------------------------------------
__global__ __launch_bounds__(128) void writeK(const float* __restrict__ code,
                                              float* __restrict__ out) {
    const int blk = blockIdx.x;
    const int tid = threadIdx.x;

    if (blk >= FILL_BLOCKS) {
        if (blk < FILL_BLOCKS + COPY_BLOCKS) {
            // ---- code passthrough (dst only 4B-aligned; scalar) ----
            const int id = blk - FILL_BLOCKS;
            float* dst = out + 1 + RES_ELEMS;
            for (long long i = (long long)id * 128 + tid;
                 i < (long long)CODE_ELEMS; i += (long long)COPY_BLOCKS * 128)
                dst[i] = __ldg(code + i);
        } else {
            // ---- loss ----
            __shared__ float red[128];
            float s = 0.f;
            for (int i = tid; i < NPIX; i += 128) s += g_maxcos[i];
            red[tid] = s;
            __syncthreads();
            for (int o = 64; o > 0; o >>= 1) {
                if (tid < o) red[tid] += red[tid + o];
                __syncthreads();
            }
            if (tid == 0) out[0] = -red[0] / (float)NPIX;
        }
        return;
    }

    // ---- fill+scatter for one (b, y) ----
    const int b = blk >> 9;
    const int y = blk & 511;

    const float fy = (y + 0.5f) * 0.0625f - 0.5f;
    const float y0f = floorf(fy);
    const float wy1 = fy - y0f, wy0 = 1.f - wy1;
    const int y0 = (int)y0f;
    const int ylo = max(y0, 0), yhi = min(y0 + 1, H_IN - 1);
    const int* A0 = g_assign + b * HW + ylo * H_IN;
    const int* A1 = g_assign + b * HW + yhi * H_IN;

    // thread t<127 owns aligned f4 at rel floats [3+4t, 7+4t); t==127 owns
    // the 4 edge scalars x = {0,1,2,511}. (row base = out+1+... => +3 is 16B
    // aligned.)
    int xs[4];
    if (tid < 127) {
#pragma unroll
        for (int k = 0; k < 4; ++k) xs[k] = 4 * tid + 3 + k;
    } else {
        xs[0] = 0; xs[1] = 1; xs[2] = 2; xs[3] = 511;
    }

    int   id[4][4];
    float w[4][4];
    unsigned long long mask = 0ull;
#pragma unroll
    for (int k = 0; k < 4; ++k) {
        const int x = xs[k];
        const float fx = (x + 0.5f) * 0.0625f - 0.5f;
        const float x0f = floorf(fx);
        const float wx1 = fx - x0f, wx0 = 1.f - wx1;
        const int x0 = (int)x0f;
        const int xlo = max(x0, 0), xhi = min(x0 + 1, H_IN - 1);
        id[k][0] = __ldg(A0 + xlo); w[k][0] = wy0 * wx0;
        id[k][1] = __ldg(A0 + xhi); w[k][1] = wy0 * wx1;
        id[k][2] = __ldg(A1 + xlo); w[k][2] = wy1 * wx0;
        id[k][3] = __ldg(A1 + xhi); w[k][3] = wy1 * wx1;
        mask |= 1ull << id[k][0];
        mask |= 1ull << id[k][1];
        mask |= 1ull << id[k][2];
        mask |= 1ull << id[k][3];
    }

    float* base = out + 1 + (size_t)b * N_CLUS * PLANE + (size_t)y * OUT_HW;
    const int slot = 3 + 4 * tid;

#pragma unroll 4
    for (int n = 0; n < N_CLUS; ++n) {
        float4 v = make_float4(0.f, 0.f, 0.f, 0.f);
        if ((mask >> n) & 1ull) {
            float r[4];
#pragma unroll
            for (int k = 0; k < 4; ++k) {
                float s = 0.f;
#pragma unroll
                for (int q = 0; q < 4; ++q)
                    s += (id[k][q] == n) ? w[k][q] : 0.f;
                r[k] = s;
            }
            v = make_float4(r[0], r[1], r[2], r[3]);
        }
        float* row = base + (size_t)n * PLANE;
        if (tid < 127) {
            __stcs((float4*)(row + slot), v);
        } else {
            __stcs(row + 0, v.x);
            __stcs(row + 1, v.y);
            __stcs(row + 2, v.z);
            __stcs(row + 511, v.w);
        }
    }
}

// ---------------------------------------------------------------------------
// out layout = [loss(1)] [resized(134217728)] [code(6291456)]
// ---------------------------------------------------------------------------
extern "C" void kernel_launch(void* const* d_in, const int* in_sizes, int n_in,
                              void* d_out, int out_size) {
    const float* code = (const float*)d_in[0];
    const float* clusters = (const float*)d_in[1];
    float* out = (float*)d_out;

    simK<<<256, 128>>>(code, clusters);
    writeK<<<W_BLOCKS, 128>>>(code, out);
}

// round 11
// speedup vs baseline: 1.5316x; 1.1573x over previous
#include <cuda_runtime.h>
#include <math.h>

#define N_CLUS 64
#define C_DIM 768
#define B_DIM 8
#define H_IN 32
#define HW 1024                          // 32*32
#define OUT_HW 512
#define PLANE (OUT_HW * OUT_HW)          // 262144
#define NPIX (B_DIM * HW)                // 8192
#define RES_ELEMS ((size_t)B_DIM * N_CLUS * PLANE)   // 134217728
#define CODE_ELEMS ((size_t)B_DIM * C_DIM * HW)      // 6291456
#define KC 32
#define KHALF 384                        // K per sim block

#define FILL_BLOCKS 4096                 // writeK: one per (b, y)
#define COPY_BLOCKS 128
#define W_BLOCKS (FILL_BLOCKS + COPY_BLOCKS + 1)   // +1 loss block
// copy: dst floats [3, 6291455) as float4 (dst+3 is 16B aligned), scalars 0,1,2 + last
#define COPY_Q4 1572863

__device__ float g_nclus[N_CLUS * C_DIM];
__device__ float g_part[2 * 128 * 64 * 64];   // [half][grp][n][px] 4MB
__device__ float g_ssqp[2 * NPIX];            // [half][px]
__device__ int   g_assign[NPIX];
__device__ float g_maxcos[NPIX];

// ---- packed fp32x2 helpers (Blackwell FFMA2) ----
__device__ __forceinline__ unsigned long long splat2(float x) {
    unsigned long long r;
    unsigned u = __float_as_uint(x);
    asm("mov.b64 %0, {%1, %2};" : "=l"(r) : "r"(u), "r"(u));
    return r;
}
__device__ __forceinline__ float2 unpack2(unsigned long long v) {
    unsigned lo, hi;
    asm("mov.b64 {%0, %1}, %2;" : "=r"(lo), "=r"(hi) : "l"(v));
    return make_float2(__uint_as_float(lo), __uint_as_float(hi));
}
#define FMA2(d, a, b) \
    asm("fma.rn.f32x2 %0, %1, %2, %0;" : "+l"(d) : "l"(a), "l"(b))

// ---------------------------------------------------------------------------
// normK: L2-normalize cluster centroids once. 64 blocks x 256 threads.
// ---------------------------------------------------------------------------
__global__ void normK(const float* __restrict__ clusters) {
    const int r = blockIdx.x;
    __shared__ float red[256];
    float s = 0.f;
    for (int i = threadIdx.x; i < C_DIM; i += 256) {
        float v = clusters[r * C_DIM + i];
        s = fmaf(v, v, s);
    }
    red[threadIdx.x] = s;
    __syncthreads();
    for (int o = 128; o > 0; o >>= 1) {
        if (threadIdx.x < o) red[threadIdx.x] += red[threadIdx.x + o];
        __syncthreads();
    }
    const float inv = 1.f / fmaxf(sqrtf(red[0]), 1e-12f);
    for (int i = threadIdx.x; i < C_DIM; i += 256)
        g_nclus[r * C_DIM + i] = clusters[r * C_DIM + i] * inv;
}

// ---------------------------------------------------------------------------
// simPartK: partial cosine dots over one K-half. 256 blocks x 256 thr.
// blk = grp(128 px-groups of 64) x half(2). Thread = 4 px x 4 clusters,
// R7-proven FFMA2 inner loop. Epilogue: smem transpose -> n-major partials.
// ---------------------------------------------------------------------------
__global__ __launch_bounds__(256) void simPartK(const float* __restrict__ code) {
    const int tid = threadIdx.x;
    const int blk = blockIdx.x;
    const int half = blk & 1;
    const int grp = blk >> 1;

    __shared__ __align__(16) float codeS[KC][64];
    __shared__ __align__(16) float clusG[16][132];   // [ng][c*4+j], pad->132
    __shared__ float pT[64 * 65];                    // [n][px], pitch 65

    const int b = grp >> 4;                  // 16 groups per image
    const int hwbase = (grp & 15) * 64;
    const int pid = tid >> 4;                // pixel quad: px 4*pid..4*pid+3
    const int ng = tid & 15;                 // cluster group: n = 4*ng..4*ng+3
    const float* codeb = code + (size_t)b * C_DIM * HW + hwbase;
    const int cbase = half * KHALF;

    unsigned long long acc2[4][2];
#pragma unroll
    for (int p = 0; p < 4; ++p) { acc2[p][0] = 0ull; acc2[p][1] = 0ull; }
    float ssq[4] = {0.f, 0.f, 0.f, 0.f};

    for (int cc = 0; cc < KHALF; cc += KC) {
        const int c0 = cbase + cc;
#pragma unroll
        for (int k = 0; k < 8; ++k) {        // stage code [KC][64], coalesced
            int idx = tid + k * 256;
            int c = idx >> 6, px = idx & 63;
            codeS[c][px] = codeb[(size_t)(c0 + c) * HW + px];
        }
#pragma unroll
        for (int k = 0; k < 8; ++k) {        // stage pre-normed clusters
            int idx = tid + k * 256;
            int g = idx >> 7, rr = idx & 127;
            int j = rr & 3, c = rr >> 2;
            clusG[g][c * 4 + j] = g_nclus[(g * 4 + j) * C_DIM + c0 + c];
        }
        __syncthreads();

#pragma unroll 4
        for (int c = 0; c < KC; ++c) {
            float4 a = *(const float4*)&codeS[c][4 * pid];
            ulonglong2 bp = *(const ulonglong2*)&clusG[ng][4 * c];
            if (ng == 0) {                   // fold feature sumsq (this half)
                ssq[0] = fmaf(a.x, a.x, ssq[0]);
                ssq[1] = fmaf(a.y, a.y, ssq[1]);
                ssq[2] = fmaf(a.z, a.z, ssq[2]);
                ssq[3] = fmaf(a.w, a.w, ssq[3]);
            }
            unsigned long long ax = splat2(a.x), ay = splat2(a.y);
            unsigned long long az = splat2(a.z), aw = splat2(a.w);
            FMA2(acc2[0][0], ax, bp.x);  FMA2(acc2[0][1], ax, bp.y);
            FMA2(acc2[1][0], ay, bp.x);  FMA2(acc2[1][1], ay, bp.y);
            FMA2(acc2[2][0], az, bp.x);  FMA2(acc2[2][1], az, bp.y);
            FMA2(acc2[3][0], aw, bp.x);  FMA2(acc2[3][1], aw, bp.y);
        }
        __syncthreads();
    }

    // epilogue: transpose to n-major in smem, then coalesced global write
#pragma unroll
    for (int p = 0; p < 4; ++p) {
        float2 j01 = unpack2(acc2[p][0]);
        float2 j23 = unpack2(acc2[p][1]);
        const int px = 4 * pid + p;
        pT[(4 * ng + 0) * 65 + px] = j01.x;
        pT[(4 * ng + 1) * 65 + px] = j01.y;
        pT[(4 * ng + 2) * 65 + px] = j23.x;
        pT[(4 * ng + 3) * 65 + px] = j23.y;
        if (ng == 0) g_ssqp[half * NPIX + grp * 64 + px] = ssq[p];
    }
    __syncthreads();

    float* dst = g_part + (size_t)(half * 128 + grp) * 4096;
#pragma unroll
    for (int k = 0; k < 16; ++k) {
        int idx = tid + k * 256;
        int n = idx >> 6, px = idx & 63;
        dst[idx] = pT[n * 65 + px];
    }
}

// ---------------------------------------------------------------------------
// argmaxK: combine K-halves, per-pixel argmax + maxcos. 32 blocks x 256 thr.
// ---------------------------------------------------------------------------
__global__ void argmaxK() {
    const int px = blockIdx.x * 256 + threadIdx.x;
    const int grp = px >> 6, pxl = px & 63;
    const float* p0 = g_part + (size_t)grp * 4096 + pxl;
    const float* p1 = g_part + (size_t)(128 + grp) * 4096 + pxl;

    float mv = -3.4e38f;
    int mn = 0;
#pragma unroll 8
    for (int n = 0; n < N_CLUS; ++n) {       // ascending n, strict > => first-max
        float s = __ldg(p0 + n * 64) + __ldg(p1 + n * 64);
        if (s > mv) { mv = s; mn = n; }
    }
    const float ssq = g_ssqp[px] + g_ssqp[NPIX + px];
    g_assign[px] = mn;
    g_maxcos[px] = mv / fmaxf(sqrtf(ssq), 1e-12f);
}

// ---------------------------------------------------------------------------
// writeK (R7 structure, plain stores): single-pass direct write + copy + loss.
//   blocks [0,4096):      (b,y) row across all 64 planes. Thread owns one
//                         aligned float4 slot; precomputes bilinear candidates
//                         + 64-bit nonzero-plane mask; 1 STG.128 per plane.
//   blocks [4096,4224):   code passthrough copy (vectorized stores)
//   block  4224:          deterministic loss reduction
// ---------------------------------------------------------------------------
__global__ __launch_bounds__(128) void writeK(const float* __restrict__ code,
                                              float* __restrict__ out) {
    const int blk = blockIdx.x;
    const int tid = threadIdx.x;

    if (blk >= FILL_BLOCKS) {
        if (blk < FILL_BLOCKS + COPY_BLOCKS) {
            // ---- code passthrough: dst+3 is 16B aligned -> STG.128 body ----
            const int id = blk - FILL_BLOCKS;
            float* dst = out + 1 + RES_ELEMS;
            if (id == 0 && tid < 4) {
                int i = (tid == 3) ? (int)(CODE_ELEMS - 1) : tid;
                dst[i] = __ldg(code + i);
            }
            for (long long q = (long long)id * 128 + tid; q < COPY_Q4;
                 q += (long long)COPY_BLOCKS * 128) {
                const float* s = code + 3 + 4 * q;
                float4 v = make_float4(__ldg(s), __ldg(s + 1),
                                       __ldg(s + 2), __ldg(s + 3));
                *(float4*)(dst + 3 + 4 * q) = v;
            }
        } else {
            // ---- loss ----
            __shared__ float red[128];
            float s = 0.f;
            for (int i = tid; i < NPIX; i += 128) s += g_maxcos[i];
            red[tid] = s;
            __syncthreads();
            for (int o = 64; o > 0; o >>= 1) {
                if (tid < o) red[tid] += red[tid + o];
                __syncthreads();
            }
            if (tid == 0) out[0] = -red[0] / (float)NPIX;
        }
        return;
    }

    // ---- fill+scatter for one (b, y) ----
    const int b = blk >> 9;
    const int y = blk & 511;

    const float fy = (y + 0.5f) * 0.0625f - 0.5f;
    const float y0f = floorf(fy);
    const float wy1 = fy - y0f, wy0 = 1.f - wy1;
    const int y0 = (int)y0f;
    const int ylo = max(y0, 0), yhi = min(y0 + 1, H_IN - 1);
    const int* A0 = g_assign + b * HW + ylo * H_IN;
    const int* A1 = g_assign + b * HW + yhi * H_IN;

    // thread t<127 owns aligned f4 at rel floats [3+4t, 7+4t); t==127 owns
    // the 4 edge scalars x = {0,1,2,511}. (row base = out+1+... => +3 is 16B
    // aligned.)
    int xs[4];
    if (tid < 127) {
#pragma unroll
        for (int k = 0; k < 4; ++k) xs[k] = 4 * tid + 3 + k;
    } else {
        xs[0] = 0; xs[1] = 1; xs[2] = 2; xs[3] = 511;
    }

    int   id[4][4];
    float w[4][4];
    unsigned long long mask = 0ull;
#pragma unroll
    for (int k = 0; k < 4; ++k) {
        const int x = xs[k];
        const float fx = (x + 0.5f) * 0.0625f - 0.5f;
        const float x0f = floorf(fx);
        const float wx1 = fx - x0f, wx0 = 1.f - wx1;
        const int x0 = (int)x0f;
        const int xlo = max(x0, 0), xhi = min(x0 + 1, H_IN - 1);
        id[k][0] = __ldg(A0 + xlo); w[k][0] = wy0 * wx0;
        id[k][1] = __ldg(A0 + xhi); w[k][1] = wy0 * wx1;
        id[k][2] = __ldg(A1 + xlo); w[k][2] = wy1 * wx0;
        id[k][3] = __ldg(A1 + xhi); w[k][3] = wy1 * wx1;
        mask |= 1ull << id[k][0];
        mask |= 1ull << id[k][1];
        mask |= 1ull << id[k][2];
        mask |= 1ull << id[k][3];
    }

    float* base = out + 1 + (size_t)b * N_CLUS * PLANE + (size_t)y * OUT_HW;
    const int slot = 3 + 4 * tid;

#pragma unroll 4
    for (int n = 0; n < N_CLUS; ++n) {
        float4 v = make_float4(0.f, 0.f, 0.f, 0.f);
        if ((mask >> n) & 1ull) {
            float r[4];
#pragma unroll
            for (int k = 0; k < 4; ++k) {
                float s = 0.f;
#pragma unroll
                for (int q = 0; q < 4; ++q)
                    s += (id[k][q] == n) ? w[k][q] : 0.f;
                r[k] = s;
            }
            v = make_float4(r[0], r[1], r[2], r[3]);
        }
        float* row = base + (size_t)n * PLANE;
        if (tid < 127) {
            *(float4*)(row + slot) = v;      // plain STG.128 (no .cs)
        } else {
            row[0] = v.x;
            row[1] = v.y;
            row[2] = v.z;
            row[511] = v.w;
        }
    }
}

// ---------------------------------------------------------------------------
// out layout = [loss(1)] [resized(134217728)] [code(6291456)]
// ---------------------------------------------------------------------------
extern "C" void kernel_launch(void* const* d_in, const int* in_sizes, int n_in,
                              void* d_out, int out_size) {
    const float* code = (const float*)d_in[0];
    const float* clusters = (const float*)d_in[1];
    float* out = (float*)d_out;

    normK<<<64, 256>>>(clusters);
    simPartK<<<256, 256>>>(code);
    argmaxK<<<32, 256>>>();
    writeK<<<W_BLOCKS, 128>>>(code, out);
}